// round 3
// baseline (speedup 1.0000x reference)
#include <cuda_runtime.h>
#include <math.h>

#define BB 8
#define NQ 1024
#define NK 256
#define HH 8
#define DFEAT 528

__constant__ int c_cg[11]    = {0,1,1,1,2,2,2,3,3,3,3};
__constant__ int c_jsmap[16] = {0,-1,1,2,3,-1,-1,-1,4,5,6,8,9,10,7,-1};
__constant__ int c_grade[16] = {0,1,1,1,1,2,2,2,2,2,2,3,3,3,3,4};

__device__ float g_WqT [5*48*384];
__device__ float g_WkvT[5*48*768];
__device__ float g_WoT [5*384*48];
__device__ float g_sp  [8];
__device__ float g_kfeat[(size_t)BB*HH*DFEAT*NK];
__device__ float g_kbias[BB*HH*NK];
__device__ float g_vtmp [(size_t)BB*HH*48*16*NK];
__device__ float g_vproj[(size_t)BB*HH*NK*768];
__device__ float g_attn [(size_t)BB*NQ*HH*NK];

typedef unsigned long long u64;
__device__ __forceinline__ u64 pk2(float lo, float hi){
    u64 u; asm("mov.b64 %0,{%1,%2};" : "=l"(u) : "f"(lo), "f"(hi)); return u;
}
__device__ __forceinline__ void upk2(u64 u, float& lo, float& hi){
    asm("mov.b64 {%0,%1},%2;" : "=f"(lo), "=f"(hi) : "l"(u));
}
__device__ __forceinline__ u64 f2fma(u64 a, u64 b, u64 c){
    u64 d; asm("fma.rn.f32x2 %0,%1,%2,%3;" : "=l"(d) : "l"(a), "l"(b), "l"(c)); return d;
}

// ===================== K0: weight transposes + softplus =====================
__global__ void k0_prep(const float* __restrict__ Wq, const float* __restrict__ Wkv,
                        const float* __restrict__ Wo, const float* __restrict__ daa){
    int stride = gridDim.x * blockDim.x;
    int gid = blockIdx.x * blockDim.x + threadIdx.x;
    for (int idx = gid; idx < 5*384*48; idx += stride){
        int g = idx/(384*48), rem = idx%(384*48), o = rem/48, i = rem%48;
        g_WqT[(g*48+i)*384+o] = Wq[idx];
    }
    for (int idx = gid; idx < 5*768*48; idx += stride){
        int g = idx/(768*48), rem = idx%(768*48), o = rem/48, i = rem%48;
        g_WkvT[(g*48+i)*768+o] = Wkv[idx];
    }
    for (int idx = gid; idx < 5*48*384; idx += stride){
        int g = idx/(48*384), rem = idx%(48*384), o = rem/384, i = rem%384;
        g_WoT[(g*384+i)*48+o] = Wo[idx];
    }
    if (gid < 8){
        float x = daa[gid];
        g_sp[gid] = (x > 20.f) ? x : log1pf(expf(x));
    }
}

// ========== K1a: kv projection, 16 keys/block -> kfeat/kbias/vtmp ==========
__global__ void __launch_bounds__(256) k1a_kv(const float* __restrict__ vision,
                                              const float* __restrict__ bkv){
    extern __shared__ float sm1[];
    float* xT  = sm1;           // [(c*48+in)][key16] pad 18 -> 768*18
    float* k2s = sm1 + 768*18;  // [h*16+key]
    int b = blockIdx.y, k0 = blockIdx.x*16, t = threadIdx.x;

    for (int idx = t; idx < 16*768; idx += 256){
        int key = idx/768, e = idx - key*768, in = e>>4, c = e&15;
        xT[(c*48+in)*18 + key] = vision[((size_t)(b*NK + k0 + key))*768 + e];
    }
    if (t < 128) k2s[t] = 0.f;
    __syncthreads();

    const float INVS = 0.051031036307982884f;  // 1/sqrt(384)
    const int GR[16] = {0,1,1,1,1,2,2,2,2,2,2,3,3,3,3,4};

    for (int s = 0; s < 3; s++){
        int o = t + 256*s;
        float bias = bkv[o];
        const float* wb = g_WkvT + o;
        for (int kt = 0; kt < 4; kt++){
            u64 acc[2][16];
            #pragma unroll
            for (int kp = 0; kp < 2; kp++){
                acc[kp][0] = pk2(bias, bias);
                #pragma unroll
                for (int c = 1; c < 16; c++) acc[kp][c] = 0ull;
            }
            #pragma unroll 4
            for (int in = 0; in < 48; in++){
                float w0 = wb[(0*48+in)*768], w1 = wb[(1*48+in)*768];
                float w2 = wb[(2*48+in)*768], w3 = wb[(3*48+in)*768];
                float w4 = wb[(4*48+in)*768];
                u64 wv[5] = {pk2(w0,w0), pk2(w1,w1), pk2(w2,w2), pk2(w3,w3), pk2(w4,w4)};
                #pragma unroll
                for (int c = 0; c < 16; c++){
                    const float* xp = xT + (c*48+in)*18 + kt*4;
                    acc[0][c] = f2fma(*(const u64*)(xp    ), wv[GR[c]], acc[0][c]);
                    acc[1][c] = f2fma(*(const u64*)(xp + 2), wv[GR[c]], acc[1][c]);
                }
            }
            if (o < 384){
                int h = o/48, i = o - h*48;
                float sp = g_sp[h], spc = sp*(2.f/48.f);
                float* kb = g_kfeat + (size_t)((b*HH+h)*DFEAT)*NK + (k0 + kt*4);
                const int IC[8] = {0,2,3,4,8,9,10,14};
                #pragma unroll
                for (int js = 0; js < 8; js++)
                    #pragma unroll
                    for (int kp = 0; kp < 2; kp++){
                        float lo, hi; upk2(acc[kp][IC[js]], lo, hi);
                        *(u64*)&kb[(size_t)(js*48+i)*NK + 2*kp] = pk2(lo*INVS, hi*INVS);
                    }
                const int PC[3] = {11,12,13};
                float s2[4] = {0.f,0.f,0.f,0.f};
                #pragma unroll
                for (int jp = 0; jp < 3; jp++)
                    #pragma unroll
                    for (int kp = 0; kp < 2; kp++){
                        float lo, hi; upk2(acc[kp][PC[jp]], lo, hi);
                        *(u64*)&kb[(size_t)((8+jp)*48+i)*NK + 2*kp] = pk2(lo*spc, hi*spc);
                        s2[2*kp] += lo*lo; s2[2*kp+1] += hi*hi;
                    }
                #pragma unroll
                for (int kk = 0; kk < 4; kk++) atomicAdd(&k2s[h*16 + kt*4 + kk], s2[kk]);
            } else {
                int vc = o - 384, h = vc/48, i = vc - h*48;
                float* vb = g_vtmp + (size_t)(((b*HH+h)*48+i)*16)*NK + (k0 + kt*4);
                #pragma unroll
                for (int c = 0; c < 16; c++){
                    *(u64*)&vb[(size_t)c*NK]     = acc[0][c];
                    *(u64*)&vb[(size_t)c*NK + 2] = acc[1][c];
                }
            }
        }
    }
    __syncthreads();
    if (t < 128){
        int h = t>>4, key = t&15;
        g_kbias[(b*HH+h)*NK + k0 + key] = -g_sp[h]*k2s[t]*(1.f/48.f);
    }
}

// ========== K1b: vproj = Wo-folded values (smem GEMM per (b,h)) ============
__global__ void __launch_bounds__(256) k1b_vproj(){
    extern __shared__ float sm2[];
    float* w_s = sm2;            // [g][i*48+o48]  5*2304
    float* v_s = sm2 + 11520;    // [(i*16+c)][key16] pad 18 -> 768*18
    int sl = blockIdx.x, h = blockIdx.y, b = blockIdx.z, t = threadIdx.x;

    for (int idx = t; idx < 11520; idx += 256){
        int g = idx/2304, r = idx - g*2304;
        w_s[idx] = g_WoT[(g*384 + h*48)*48 + r];
    }
    int j = sl*256 + t;
    int o48 = j>>4, c = j&15, g = c_grade[c];
    const size_t vbase = (size_t)((b*HH+h)*48)*16*NK;

    for (int kt = 0; kt < 16; kt++){
        __syncthreads();
        for (int idx = t; idx < 12288; idx += 256){
            int key = idx&15, rr = idx>>4;
            v_s[rr*18 + key] = g_vtmp[vbase + (size_t)rr*NK + kt*16 + key];
        }
        __syncthreads();
        u64 acc[8];
        #pragma unroll
        for (int kp = 0; kp < 8; kp++) acc[kp] = 0ull;
        #pragma unroll 4
        for (int i = 0; i < 48; i++){
            float ww = w_s[g*2304 + i*48 + o48];
            u64 w2 = pk2(ww, ww);
            const float* vp = v_s + (i*16+c)*18;
            #pragma unroll
            for (int kp = 0; kp < 8; kp++)
                acc[kp] = f2fma(*(const u64*)(vp + 2*kp), w2, acc[kp]);
        }
        float* dst = g_vproj + (size_t)((b*HH+h)*NK + kt*16)*768 + j;
        #pragma unroll
        for (int kp = 0; kp < 8; kp++){
            float lo, hi; upk2(acc[kp], lo, hi);
            dst[(size_t)(2*kp)*768]   = lo;
            dst[(size_t)(2*kp+1)*768] = hi;
        }
    }
}

// ===================== K2: rmsnorm + q proj + logits + softmax ==============
__global__ void __launch_bounds__(256) k2_attn(const float* __restrict__ hidden,
                                               const float* __restrict__ lnw,
                                               const float* __restrict__ bq){
    extern __shared__ float sm[];
    float* sm_xc  = sm;                  // 11*48*34 = 17952
    float* sm_qT  = sm + 17952;          // 528*34   = 17952
    float* sm_w   = sm_qT + 17952;       // 4*2304   = 9216
    float* sm_red = sm_w + 9216;         // 256
    float* sm_rs  = sm_red + 256;        // 32
    float* sm_rsq = sm_rs + 32;          // 32
    int b = blockIdx.y, q0 = blockIdx.x*32, t = threadIdx.x;
    int lane = t&31, w = t>>5;
    const float* hrow = hidden + (size_t)(b*NQ+q0)*768;

    { int r = t>>3, sub = t&7; float s = 0.f;
      for (int e = sub; e < 768; e += 8){ float v = hrow[r*768+e]; s += v*v; }
      s += __shfl_xor_sync(~0u, s, 1);
      s += __shfl_xor_sync(~0u, s, 2);
      s += __shfl_xor_sync(~0u, s, 4);
      if (sub == 0) sm_rsq[r] = rsqrtf(s*(1.f/48.f) + 1e-6f);
    }
    __syncthreads();
    for (int idx = t; idx < 32*768; idx += 256){
        int r = idx/768, e = idx - r*768, in = e>>4, c = e&15;
        int js = c_jsmap[c];
        if (js >= 0) sm_xc[(js*48+in)*34 + r] = hrow[idx]*sm_rsq[r]*lnw[in];
    }

    for (int h = 0; h < HH; h++){
        __syncthreads();
        for (int idx = t; idx < 9216; idx += 256){
            int g = idx/2304, r = idx - g*2304, in = r/48, i = r - in*48;
            sm_w[idx] = g_WqT[(g*48+in)*384 + h*48 + i];
        }
        __syncthreads();

        // ---- phase B: qfeat via smem weights, f32x2 row pairs ----
        #pragma unroll
        for (int mi = 0; mi < 3; mi++){
            int m = t + 256*mi;
            if (m < 528){
                int js = m/48, i = m - js*48, g = c_cg[js];
                float bias = (js == 0) ? bq[h*48+i] : 0.f;
                u64 acc[16];
                u64 b2 = pk2(bias, bias);
                #pragma unroll
                for (int p = 0; p < 16; p++) acc[p] = b2;
                const float* wp = sm_w + g*2304 + i;
                const float* xp = sm_xc + (js*48)*34;
                #pragma unroll 4
                for (int in = 0; in < 48; in++){
                    float ww = wp[in*48];
                    u64 w2 = pk2(ww, ww);
                    const float* xr = xp + in*34;
                    #pragma unroll
                    for (int p = 0; p < 16; p++)
                        acc[p] = f2fma(*(const u64*)(xr + 2*p), w2, acc[p]);
                }
                #pragma unroll
                for (int p = 0; p < 16; p++) *(u64*)&sm_qT[m*34 + 2*p] = acc[p];
            }
        }
        __syncthreads();

        // ---- phase C: logits (thread = key) ----
        u64 acc[16];
        { float kb = g_kbias[(b*HH+h)*NK + t];
          u64 kb2 = pk2(kb, kb);
          #pragma unroll
          for (int p = 0; p < 16; p++) acc[p] = kb2; }
        const float* kcol = g_kfeat + (size_t)((b*HH+h)*DFEAT)*NK + t;
        #pragma unroll 2
        for (int d = 0; d < DFEAT; d++){
            float kf = kcol[(size_t)d*NK];
            u64 kf2 = pk2(kf, kf);
            const float* qr = sm_qT + d*34;
            #pragma unroll
            for (int p = 0; p < 16; p++)
                acc[p] = f2fma(*(const u64*)(qr + 2*p), kf2, acc[p]);
        }

        // ---- phase D: softmax over k ----
        float a[32];
        #pragma unroll
        for (int p = 0; p < 16; p++) upk2(acc[p], a[2*p], a[2*p+1]);
        #pragma unroll
        for (int r = 0; r < 32; r++){
            float m = a[r];
            #pragma unroll
            for (int off = 16; off > 0; off >>= 1) m = fmaxf(m, __shfl_xor_sync(~0u, m, off));
            if (lane == 0) sm_red[r*8 + w] = m;
        }
        __syncthreads();
        if (t < 32){
            float m = sm_red[t*8];
            #pragma unroll
            for (int jj = 1; jj < 8; jj++) m = fmaxf(m, sm_red[t*8 + jj]);
            sm_rs[t] = m;
        }
        __syncthreads();
        #pragma unroll
        for (int r = 0; r < 32; r++){
            a[r] = __expf(a[r] - sm_rs[r]);
            float s = a[r];
            #pragma unroll
            for (int off = 16; off > 0; off >>= 1) s += __shfl_xor_sync(~0u, s, off);
            if (lane == 0) sm_red[r*8 + w] = s;
        }
        __syncthreads();
        if (t < 32){
            float s = 0.f;
            #pragma unroll
            for (int jj = 0; jj < 8; jj++) s += sm_red[t*8 + jj];
            sm_rs[t] = 1.f / s;
        }
        __syncthreads();

        float* arow = g_attn + (size_t)(b*NQ+q0)*2048 + h*NK + t;
        #pragma unroll
        for (int r = 0; r < 32; r++) arow[(size_t)r*2048] = a[r]*sm_rs[r];
    }
}

// ===================== K3: out = hidden + bo*e0 + attn @ vproj ==============
__global__ void __launch_bounds__(192) k3_av(const float* __restrict__ hidden,
                                             const float* __restrict__ bo,
                                             float* __restrict__ out){
    __shared__ float asm_[128*18];   // [hk128][rowpair16] padded
    int b = blockIdx.y, q0 = blockIdx.x*16, t = threadIdx.x;
    int oc = 4*t;

    u64 acc[32];                     // [col4][pair8]
    #pragma unroll
    for (int p = 0; p < 32; p++) acc[p] = 0ull;

    const float* ab = g_attn  + (size_t)(b*NQ+q0)*2048;
    const float* vb = g_vproj + (size_t)b*2048*768 + oc;

    for (int hk0 = 0; hk0 < 2048; hk0 += 128){
        __syncthreads();
        for (int idx = t; idx < 2048; idx += 192){
            int hl = idx & 127, r = idx >> 7;
            asm_[hl*18 + r] = ab[(size_t)r*2048 + hk0 + hl];
        }
        __syncthreads();
        #pragma unroll 2
        for (int hl = 0; hl < 128; hl++){
            float4 v4 = *(const float4*)&vb[(size_t)(hk0+hl)*768];
            u64 v2[4] = {pk2(v4.x,v4.x), pk2(v4.y,v4.y), pk2(v4.z,v4.z), pk2(v4.w,v4.w)};
            const float* ar = asm_ + hl*18;
            #pragma unroll
            for (int p = 0; p < 8; p++){
                u64 a2 = *(const u64*)(ar + 2*p);
                acc[0*8+p] = f2fma(a2, v2[0], acc[0*8+p]);
                acc[1*8+p] = f2fma(a2, v2[1], acc[1*8+p]);
                acc[2*8+p] = f2fma(a2, v2[2], acc[2*8+p]);
                acc[3*8+p] = f2fma(a2, v2[3], acc[3*8+p]);
            }
        }
    }

    const float* hb = hidden + (size_t)(b*NQ+q0)*768;
    float*       ob = out    + (size_t)(b*NQ+q0)*768;
    #pragma unroll
    for (int cc = 0; cc < 4; cc++){
        int col = oc + cc;
        float bias = ((col & 15) == 0) ? bo[col >> 4] : 0.f;
        #pragma unroll
        for (int p = 0; p < 8; p++){
            float lo, hi; upk2(acc[cc*8+p], lo, hi);
            ob[(size_t)(2*p  )*768 + col] = hb[(size_t)(2*p  )*768 + col] + lo + bias;
            ob[(size_t)(2*p+1)*768 + col] = hb[(size_t)(2*p+1)*768 + col] + hi + bias;
        }
    }
}

// ===========================================================================
extern "C" void kernel_launch(void* const* d_in, const int* in_sizes, int n_in,
                              void* d_out, int out_size){
    const float* hidden = (const float*)d_in[0];
    const float* vision = (const float*)d_in[1];
    const float* lnw    = (const float*)d_in[2];
    const float* Wq     = (const float*)d_in[3];
    const float* bq     = (const float*)d_in[4];
    const float* Wkv    = (const float*)d_in[5];
    const float* bkv    = (const float*)d_in[6];
    const float* Wo     = (const float*)d_in[7];
    const float* bo     = (const float*)d_in[8];
    const float* daa    = (const float*)d_in[9];
    float* out = (float*)d_out;

    const int s1a = (768*18 + 128)*4;
    const int s1b = (11520 + 768*18)*4;
    const int s2  = (17952 + 17952 + 9216 + 256 + 32 + 32)*4;
    cudaFuncSetAttribute(k1a_kv,   cudaFuncAttributeMaxDynamicSharedMemorySize, s1a);
    cudaFuncSetAttribute(k1b_vproj,cudaFuncAttributeMaxDynamicSharedMemorySize, s1b);
    cudaFuncSetAttribute(k2_attn,  cudaFuncAttributeMaxDynamicSharedMemorySize, s2);

    k0_prep  <<<128, 256>>>(Wq, Wkv, Wo, daa);
    k1a_kv   <<<dim3(NK/16, BB), 256, s1a>>>(vision, bkv);
    k1b_vproj<<<dim3(3, HH, BB), 256, s1b>>>();
    k2_attn  <<<dim3(NQ/32, BB), 256, s2>>>(hidden, lnw, bq);
    k3_av    <<<dim3(NQ/16, BB), 192>>>(hidden, bo, out);
}

// round 6
// speedup vs baseline: 3.3420x; 3.3420x over previous
#include <cuda_runtime.h>
#include <math.h>
#include <stdint.h>

#define BB 8
#define NQ 1024
#define NK 256
#define HH 8
#define DF 528
#define DFP 576

typedef unsigned long long u64;
typedef unsigned int u32;

__constant__ int c_cg[11]    = {0,1,1,1,2,2,2,3,3,3,3};
__constant__ int c_jsmap[16] = {0,-1,1,2,3,-1,-1,-1,4,5,6,8,9,10,7,-1};
__constant__ int c_grade[16] = {0,1,1,1,1,2,2,2,2,2,2,3,3,3,3,4};

__device__ float g_WqT [5*48*384];
__device__ float g_WkvT[5*48*768];
__device__ float g_WoT [5*384*48];
__device__ float g_sp  [8];
__device__ float g_qfeat [(size_t)BB*HH*NQ*DFP];
__device__ float g_kfeatT[(size_t)BB*HH*NK*DFP];
__device__ float g_vtmp  [(size_t)BB*HH*48*16*NK];
__device__ float g_vprojT[(size_t)BB*768*2048];
__device__ float g_attn  [(size_t)BB*NQ*2048];

__device__ __forceinline__ u64 pk2(float lo, float hi){
    u64 u; asm("mov.b64 %0,{%1,%2};" : "=l"(u) : "f"(lo), "f"(hi)); return u;
}
__device__ __forceinline__ void upk2(u64 u, float& lo, float& hi){
    asm("mov.b64 {%0,%1},%2;" : "=f"(lo), "=f"(hi) : "l"(u));
}
__device__ __forceinline__ u64 f2fma(u64 a, u64 b, u64 c){
    u64 d; asm("fma.rn.f32x2 %0,%1,%2,%3;" : "=l"(d) : "l"(a), "l"(b), "l"(c)); return d;
}
__device__ __forceinline__ u32 cvt_tf32(float x){
    u32 r; asm("cvt.rna.tf32.f32 %0,%1;" : "=r"(r) : "f"(x)); return r;
}
__device__ __forceinline__ void mma168(float* d, const u32* a, const u32* b){
    asm volatile("mma.sync.aligned.m16n8k8.row.col.f32.tf32.tf32.f32 "
        "{%0,%1,%2,%3},{%4,%5,%6,%7},{%8,%9},{%0,%1,%2,%3};"
        : "+f"(d[0]), "+f"(d[1]), "+f"(d[2]), "+f"(d[3])
        : "r"(a[0]), "r"(a[1]), "r"(a[2]), "r"(a[3]), "r"(b[0]), "r"(b[1]));
}

// ===================== K0: weight transposes + softplus =====================
__global__ void k0_prep(const float* __restrict__ Wq, const float* __restrict__ Wkv,
                        const float* __restrict__ Wo, const float* __restrict__ daa){
    int stride = gridDim.x * blockDim.x;
    int gid = blockIdx.x * blockDim.x + threadIdx.x;
    for (int idx = gid; idx < 5*384*48; idx += stride){
        int g = idx/(384*48), rem = idx%(384*48), o = rem/48, i = rem%48;
        g_WqT[(g*48+i)*384+o] = Wq[idx];
    }
    for (int idx = gid; idx < 5*768*48; idx += stride){
        int g = idx/(768*48), rem = idx%(768*48), o = rem/48, i = rem%48;
        g_WkvT[(g*48+i)*768+o] = Wkv[idx];
    }
    for (int idx = gid; idx < 5*48*384; idx += stride){
        int g = idx/(48*384), rem = idx%(48*384), o = rem/384, i = rem%384;
        g_WoT[(g*384+i)*48+o] = Wo[idx];
    }
    if (gid < 8){
        float x = daa[gid];
        g_sp[gid] = (x > 20.f) ? x : log1pf(expf(x));
    }
}

// ========== K1a: kv projection, 16 keys/block -> kfeatT(row-major)/vtmp =====
__global__ void __launch_bounds__(256) k1a_kv(const float* __restrict__ vision,
                                              const float* __restrict__ bkv){
    extern __shared__ float sm1[];
    float* xT  = sm1;           // [(c*48+in)][key16] pad 18
    float* k2s = sm1 + 768*18;  // [h*16+key]
    int b = blockIdx.y, k0 = blockIdx.x*16, t = threadIdx.x;

    for (int idx = t; idx < 16*768; idx += 256){
        int key = idx/768, e = idx - key*768, in = e>>4, c = e&15;
        xT[(c*48+in)*18 + key] = vision[((size_t)(b*NK + k0 + key))*768 + e];
    }
    if (t < 128) k2s[t] = 0.f;
    __syncthreads();

    const float INVS = 0.051031036307982884f;  // 1/sqrt(384)
    const int GR[16] = {0,1,1,1,1,2,2,2,2,2,2,3,3,3,3,4};

    for (int s = 0; s < 3; s++){
        int o = t + 256*s;
        float bias = bkv[o];
        const float* wb = g_WkvT + o;
        for (int kt = 0; kt < 4; kt++){
            u64 acc[2][16];
            #pragma unroll
            for (int kp = 0; kp < 2; kp++){
                acc[kp][0] = pk2(bias, bias);
                #pragma unroll
                for (int c = 1; c < 16; c++) acc[kp][c] = 0ull;
            }
            #pragma unroll 4
            for (int in = 0; in < 48; in++){
                float w0 = wb[(0*48+in)*768], w1 = wb[(1*48+in)*768];
                float w2 = wb[(2*48+in)*768], w3 = wb[(3*48+in)*768];
                float w4 = wb[(4*48+in)*768];
                u64 wv[5] = {pk2(w0,w0), pk2(w1,w1), pk2(w2,w2), pk2(w3,w3), pk2(w4,w4)};
                #pragma unroll
                for (int c = 0; c < 16; c++){
                    const float* xp = xT + (c*48+in)*18 + kt*4;
                    acc[0][c] = f2fma(*(const u64*)(xp    ), wv[GR[c]], acc[0][c]);
                    acc[1][c] = f2fma(*(const u64*)(xp + 2), wv[GR[c]], acc[1][c]);
                }
            }
            if (o < 384){
                int h = o/48, i = o - h*48;
                float sp = g_sp[h], spc = sp*(2.f/48.f);
                size_t rb = (size_t)((b*HH+h)*NK + k0 + kt*4)*DFP;
                const int IC[8] = {0,2,3,4,8,9,10,14};
                #pragma unroll
                for (int js = 0; js < 8; js++)
                    #pragma unroll
                    for (int kp = 0; kp < 2; kp++){
                        float lo, hi; upk2(acc[kp][IC[js]], lo, hi);
                        g_kfeatT[rb + (size_t)(2*kp  )*DFP + js*48+i] = lo*INVS;
                        g_kfeatT[rb + (size_t)(2*kp+1)*DFP + js*48+i] = hi*INVS;
                    }
                const int PC[3] = {11,12,13};
                float s2[4] = {0.f,0.f,0.f,0.f};
                #pragma unroll
                for (int jp = 0; jp < 3; jp++)
                    #pragma unroll
                    for (int kp = 0; kp < 2; kp++){
                        float lo, hi; upk2(acc[kp][PC[jp]], lo, hi);
                        g_kfeatT[rb + (size_t)(2*kp  )*DFP + 384+jp*48+i] = lo*spc;
                        g_kfeatT[rb + (size_t)(2*kp+1)*DFP + 384+jp*48+i] = hi*spc;
                        s2[2*kp] += lo*lo; s2[2*kp+1] += hi*hi;
                    }
                #pragma unroll
                for (int kk = 0; kk < 4; kk++) atomicAdd(&k2s[h*16 + kt*4 + kk], s2[kk]);
            } else {
                int vc = o - 384, h = vc/48, i = vc - h*48;
                float* vb = g_vtmp + (size_t)(((b*HH+h)*48+i)*16)*NK + (k0 + kt*4);
                #pragma unroll
                for (int c = 0; c < 16; c++){
                    *(u64*)&vb[(size_t)c*NK]     = acc[0][c];
                    *(u64*)&vb[(size_t)c*NK + 2] = acc[1][c];
                }
            }
        }
    }
    __syncthreads();
    if (t < 128){
        int h = t>>4, key = t&15;
        g_kfeatT[(size_t)((b*HH+h)*NK + k0 + key)*DFP + 528] = -g_sp[h]*k2s[t]*(1.f/48.f);
    }
    for (int idx = t; idx < 8*16*47; idx += 256){
        int h2 = idx/(16*47), rem = idx - h2*16*47, key = rem/47, cc = rem - key*47;
        g_kfeatT[(size_t)((b*HH+h2)*NK + k0 + key)*DFP + 529 + cc] = 0.f;
    }
}

// ========== K1b: vprojT[b][col768][kh2048] = Wo-folded values ==============
__global__ void __launch_bounds__(256) k1b_vproj(){
    extern __shared__ float sm2[];
    float* w_s = sm2;            // [g][i*48+o48] 5*2304
    float* v_s = sm2 + 11520;    // [(i*16+c)][key16] pad 18
    int sl = blockIdx.x, h = blockIdx.y, b = blockIdx.z, t = threadIdx.x;

    for (int idx = t; idx < 11520; idx += 256){
        int g = idx/2304, r = idx - g*2304;
        w_s[idx] = g_WoT[(g*384 + h*48)*48 + r];
    }
    int j = sl*256 + t;
    int o48 = j>>4, c = j&15, g = c_grade[c];
    const size_t vbase = (size_t)((b*HH+h)*48)*16*NK;

    for (int kt = 0; kt < 16; kt++){
        __syncthreads();
        for (int idx = t; idx < 12288; idx += 256){
            int key = idx&15, rr = idx>>4;
            v_s[rr*18 + key] = g_vtmp[vbase + (size_t)rr*NK + kt*16 + key];
        }
        __syncthreads();
        u64 acc[8];
        #pragma unroll
        for (int kp = 0; kp < 8; kp++) acc[kp] = 0ull;
        #pragma unroll 4
        for (int i = 0; i < 48; i++){
            float ww = w_s[g*2304 + i*48 + o48];
            u64 w2 = pk2(ww, ww);
            const float* vp = v_s + (i*16+c)*18;
            #pragma unroll
            for (int kp = 0; kp < 8; kp++)
                acc[kp] = f2fma(*(const u64*)(vp + 2*kp), w2, acc[kp]);
        }
        float* dst = g_vprojT + (size_t)(b*768 + j)*2048 + h*NK + kt*16;
        #pragma unroll
        for (int kp = 0; kp < 8; kp++) *(u64*)&dst[2*kp] = acc[kp];
    }
}

// ===================== K2a: rmsnorm + q projection -> g_qfeat ===============
__global__ void __launch_bounds__(256) k2a_qfeat(const float* __restrict__ hidden,
                                                 const float* __restrict__ lnw,
                                                 const float* __restrict__ bq){
    extern __shared__ float sm[];
    float* sm_xc  = sm;                  // 11*48*34
    float* sm_qT  = sm + 17952;          // 528*34
    float* sm_w   = sm_qT + 17952;       // 4*2304
    float* sm_rsq = sm_w + 9216;         // 32
    int b = blockIdx.y, q0 = blockIdx.x*32, t = threadIdx.x;
    const float* hrow = hidden + (size_t)(b*NQ+q0)*768;

    { int r = t>>3, sub = t&7; float s = 0.f;
      for (int e = sub; e < 768; e += 8){ float v = hrow[r*768+e]; s += v*v; }
      s += __shfl_xor_sync(~0u, s, 1);
      s += __shfl_xor_sync(~0u, s, 2);
      s += __shfl_xor_sync(~0u, s, 4);
      if (sub == 0) sm_rsq[r] = rsqrtf(s*(1.f/48.f) + 1e-6f);
    }
    __syncthreads();
    for (int idx = t; idx < 32*768; idx += 256){
        int r = idx/768, e = idx - r*768, in = e>>4, c = e&15;
        int js = c_jsmap[c];
        if (js >= 0) sm_xc[(js*48+in)*34 + r] = hrow[idx]*sm_rsq[r]*lnw[in];
    }

    for (int h = 0; h < HH; h++){
        __syncthreads();
        for (int idx = t; idx < 9216; idx += 256){
            int g = idx/2304, r = idx - g*2304, in = r/48, i = r - in*48;
            sm_w[idx] = g_WqT[(g*48+in)*384 + h*48 + i];
        }
        __syncthreads();
        #pragma unroll
        for (int mi = 0; mi < 3; mi++){
            int m = t + 256*mi;
            if (m < 528){
                int js = m/48, i = m - js*48, g = c_cg[js];
                float bias = (js == 0) ? bq[h*48+i] : 0.f;
                u64 acc[16];
                u64 b2 = pk2(bias, bias);
                #pragma unroll
                for (int p = 0; p < 16; p++) acc[p] = b2;
                const float* wp = sm_w + g*2304 + i;
                const float* xp = sm_xc + (js*48)*34;
                #pragma unroll 4
                for (int in = 0; in < 48; in++){
                    float ww = wp[in*48];
                    u64 w2 = pk2(ww, ww);
                    const float* xr = xp + in*34;
                    #pragma unroll
                    for (int p = 0; p < 16; p++)
                        acc[p] = f2fma(*(const u64*)(xr + 2*p), w2, acc[p]);
                }
                #pragma unroll
                for (int p = 0; p < 16; p++) *(u64*)&sm_qT[m*34 + 2*p] = acc[p];
            }
        }
        __syncthreads();
        float* qA = g_qfeat + (size_t)((b*HH+h)*NQ + q0)*DFP;
        for (int idx = t; idx < 32*DFP; idx += 256){
            int r = idx/DFP, d = idx - r*DFP;
            float val = (d < DF) ? sm_qT[d*34 + r] : ((d == DF) ? 1.f : 0.f);
            qA[(size_t)r*DFP + d] = val;
        }
    }
}

// ============ shared GEMM core: 64 rows x 256 cols, mma.sync tf32 ===========
// As: [64][36], Bs: [256][36]; warp wid owns m64 x n32 (cols wid*32..)
__device__ __forceinline__ void gemm_chunk(const float* As, const float* Bs,
                                           float acc[4][4][4], int wid, int lane){
    int g = lane >> 2, t4 = lane & 3;
    #pragma unroll
    for (int k8 = 0; k8 < 4; k8++){
        u32 au[4][4];
        #pragma unroll
        for (int mt = 0; mt < 4; mt++){
            const float* ap = As + (mt*16 + g)*36 + k8*8 + t4;
            au[mt][0] = cvt_tf32(ap[0]);
            au[mt][1] = cvt_tf32(ap[8*36]);
            au[mt][2] = cvt_tf32(ap[4]);
            au[mt][3] = cvt_tf32(ap[8*36+4]);
        }
        u32 bu[4][2];
        #pragma unroll
        for (int nt8 = 0; nt8 < 4; nt8++){
            const float* bp = Bs + (wid*32 + nt8*8 + g)*36 + k8*8 + t4;
            bu[nt8][0] = cvt_tf32(bp[0]);
            bu[nt8][1] = cvt_tf32(bp[4]);
        }
        #pragma unroll
        for (int mt = 0; mt < 4; mt++)
            #pragma unroll
            for (int nt8 = 0; nt8 < 4; nt8++)
                mma168(acc[mt][nt8], au[mt], bu[nt8]);
    }
}

// ===================== K2b: tf32 mma logits + softmax ======================
__global__ void __launch_bounds__(256) k2b_logits(){
    __shared__ float As[64*36];
    __shared__ float Bs[256*36];
    __shared__ float red[64*8];
    __shared__ float rmax[64];
    __shared__ float rsum[64];
    int t = threadIdx.x, wid = t>>5, lane = t&31;
    int g = lane>>2, t4 = lane&3;
    int qt = blockIdx.x, h = blockIdx.y, b = blockIdx.z;

    const float* Ag = g_qfeat  + (size_t)((b*HH+h)*NQ + qt*64)*DFP;
    const float* Bg = g_kfeatT + (size_t)((b*HH+h)*NK)*DFP;

    float acc[4][4][4];
    #pragma unroll
    for (int mt = 0; mt < 4; mt++)
        #pragma unroll
        for (int nt8 = 0; nt8 < 4; nt8++)
            #pragma unroll
            for (int r = 0; r < 4; r++) acc[mt][nt8][r] = 0.f;

    for (int kc = 0; kc < 18; kc++){
        #pragma unroll
        for (int it = 0; it < 2; it++){
            int i = t + 256*it;
            int row = i >> 3, kq = (i & 7)*4;
            float4 v = *(const float4*)(Ag + (size_t)row*DFP + kc*32 + kq);
            *(float4*)&As[row*36 + kq] = v;
        }
        #pragma unroll
        for (int it = 0; it < 8; it++){
            int i = t + 256*it;
            int row = i >> 3, kq = (i & 7)*4;
            float4 v = *(const float4*)(Bg + (size_t)row*DFP + kc*32 + kq);
            *(float4*)&Bs[row*36 + kq] = v;
        }
        __syncthreads();
        gemm_chunk(As, Bs, acc, wid, lane);
        __syncthreads();
    }

    // ---- softmax ----
    #pragma unroll
    for (int mt = 0; mt < 4; mt++)
        #pragma unroll
        for (int i = 0; i < 2; i++){
            float m = -1e30f;
            #pragma unroll
            for (int nt8 = 0; nt8 < 4; nt8++)
                m = fmaxf(m, fmaxf(acc[mt][nt8][2*i], acc[mt][nt8][2*i+1]));
            m = fmaxf(m, __shfl_xor_sync(~0u, m, 1));
            m = fmaxf(m, __shfl_xor_sync(~0u, m, 2));
            if (t4 == 0) red[(mt*16 + g + i*8)*8 + wid] = m;
        }
    __syncthreads();
    if (t < 64){
        float m = red[t*8];
        #pragma unroll
        for (int j = 1; j < 8; j++) m = fmaxf(m, red[t*8+j]);
        rmax[t] = m;
    }
    __syncthreads();
    #pragma unroll
    for (int mt = 0; mt < 4; mt++)
        #pragma unroll
        for (int i = 0; i < 2; i++){
            float mm = rmax[mt*16 + g + i*8];
            float s = 0.f;
            #pragma unroll
            for (int nt8 = 0; nt8 < 4; nt8++){
                float e0 = __expf(acc[mt][nt8][2*i]   - mm);
                float e1 = __expf(acc[mt][nt8][2*i+1] - mm);
                acc[mt][nt8][2*i] = e0; acc[mt][nt8][2*i+1] = e1;
                s += e0 + e1;
            }
            s += __shfl_xor_sync(~0u, s, 1);
            s += __shfl_xor_sync(~0u, s, 2);
            if (t4 == 0) red[(mt*16 + g + i*8)*8 + wid] = s;
        }
    __syncthreads();
    if (t < 64){
        float s = red[t*8];
        #pragma unroll
        for (int j = 1; j < 8; j++) s += red[t*8+j];
        rsum[t] = 1.f/s;
    }
    __syncthreads();
    #pragma unroll
    for (int mt = 0; mt < 4; mt++)
        #pragma unroll
        for (int i = 0; i < 2; i++){
            int row = mt*16 + g + i*8;
            float inv = rsum[row];
            float* dst = g_attn + (size_t)(b*NQ + qt*64 + row)*2048 + h*NK + wid*32;
            #pragma unroll
            for (int nt8 = 0; nt8 < 4; nt8++){
                float2 o = make_float2(acc[mt][nt8][2*i]*inv, acc[mt][nt8][2*i+1]*inv);
                *(float2*)(dst + nt8*8 + t4*2) = o;
            }
        }
}

// ===================== K3: tf32 mma attn @ vprojT + residual ================
__global__ void __launch_bounds__(256) k3_av(const float* __restrict__ hidden,
                                             const float* __restrict__ bo,
                                             float* __restrict__ out){
    __shared__ float As[64*36];
    __shared__ float Bs[256*36];
    int t = threadIdx.x, wid = t>>5, lane = t&31;
    int g = lane>>2, t4 = lane&3;
    int nt = blockIdx.x, qt = blockIdx.y, b = blockIdx.z;

    const float* Ag = g_attn   + (size_t)(b*NQ + qt*64)*2048;
    const float* Bg = g_vprojT + (size_t)(b*768 + nt*256)*2048;

    float acc[4][4][4];
    #pragma unroll
    for (int mt = 0; mt < 4; mt++)
        #pragma unroll
        for (int nt8 = 0; nt8 < 4; nt8++)
            #pragma unroll
            for (int r = 0; r < 4; r++) acc[mt][nt8][r] = 0.f;

    for (int kc = 0; kc < 64; kc++){
        #pragma unroll
        for (int it = 0; it < 2; it++){
            int i = t + 256*it;
            int row = i >> 3, kq = (i & 7)*4;
            float4 v = *(const float4*)(Ag + (size_t)row*2048 + kc*32 + kq);
            *(float4*)&As[row*36 + kq] = v;
        }
        #pragma unroll
        for (int it = 0; it < 8; it++){
            int i = t + 256*it;
            int row = i >> 3, kq = (i & 7)*4;
            float4 v = *(const float4*)(Bg + (size_t)row*2048 + kc*32 + kq);
            *(float4*)&Bs[row*36 + kq] = v;
        }
        __syncthreads();
        gemm_chunk(As, Bs, acc, wid, lane);
        __syncthreads();
    }

    #pragma unroll
    for (int mt = 0; mt < 4; mt++)
        #pragma unroll
        for (int i = 0; i < 2; i++){
            int row = qt*64 + mt*16 + g + i*8;
            const float* hb = hidden + (size_t)(b*NQ + row)*768;
            float*       ob = out    + (size_t)(b*NQ + row)*768;
            #pragma unroll
            for (int nt8 = 0; nt8 < 4; nt8++){
                int col = nt*256 + wid*32 + nt8*8 + t4*2;
                float2 hv = *(const float2*)(hb + col);
                float vx = acc[mt][nt8][2*i]   + hv.x;
                float vy = acc[mt][nt8][2*i+1] + hv.y;
                if ((col & 15) == 0) vx += bo[col >> 4];
                *(float2*)(ob + col) = make_float2(vx, vy);
            }
        }
}

// ===========================================================================
extern "C" void kernel_launch(void* const* d_in, const int* in_sizes, int n_in,
                              void* d_out, int out_size){
    const float* hidden = (const float*)d_in[0];
    const float* vision = (const float*)d_in[1];
    const float* lnw    = (const float*)d_in[2];
    const float* Wq     = (const float*)d_in[3];
    const float* bq     = (const float*)d_in[4];
    const float* Wkv    = (const float*)d_in[5];
    const float* bkv    = (const float*)d_in[6];
    const float* Wo     = (const float*)d_in[7];
    const float* bo     = (const float*)d_in[8];
    const float* daa    = (const float*)d_in[9];
    float* out = (float*)d_out;

    const int s1a = (768*18 + 128)*4;
    const int s1b = (11520 + 768*18)*4;
    const int s2a = (17952 + 17952 + 9216 + 32)*4;
    cudaFuncSetAttribute(k1a_kv,    cudaFuncAttributeMaxDynamicSharedMemorySize, s1a);
    cudaFuncSetAttribute(k1b_vproj, cudaFuncAttributeMaxDynamicSharedMemorySize, s1b);
    cudaFuncSetAttribute(k2a_qfeat, cudaFuncAttributeMaxDynamicSharedMemorySize, s2a);

    k0_prep   <<<128, 256>>>(Wq, Wkv, Wo, daa);
    k1a_kv    <<<dim3(NK/16, BB), 256, s1a>>>(vision, bkv);
    k1b_vproj <<<dim3(3, HH, BB), 256, s1b>>>();
    k2a_qfeat <<<dim3(NQ/32, BB), 256, s2a>>>(hidden, lnw, bq);
    k2b_logits<<<dim3(NQ/64, HH, BB), 256>>>();
    k3_av     <<<dim3(3, NQ/64, BB), 256>>>(hidden, bo, out);
}